// round 8
// baseline (speedup 1.0000x reference)
#include <cuda_runtime.h>
#include <cuda_fp16.h>

// GPTQ int4 dequant GEMM via HMMA: out[32,8192] = x @ dequant(W)^T + bias
// M=32, K=8192, N=8192, group=64. packed int32 element = one byte = 2 k-nibbles.
// v8: MMA on raw biased nibbles (1024+q, exact in fp16, 3 ALU ops/byte); per-group
// algebraic fixup acc += s*accg - s*(z+1024)*X_g[row] with s,z applied at the
// accumulator's TRUE columns n = 2*(l&3)+{0,1} (v7 used l>>2 -- the bug) via an
// 8KB smem LUT. v5's 2-deep cp.async ring (fastest schedule so far). red.v2 epilogue.

#define MM 32
#define KDIM 8192
#define NDIM 8192
#define GS 64
#define NGROUPS 128
#define NTHREADS 256
#define NBLK 128           // n per CTA
#define KSPLIT 16
#define KPER 512           // k per CTA
#define GROUPS_PER 8       // KPER / GS
#define WROW 36            // int32 per ws row (32 data + 4 pad = 144B stride)
#define WBUF (NBLK * WROW) // int32 per ring buffer (one group)
#define WS_BYTES (2 * WBUF * 4)
#define XROWH 520          // halfs per xs row (512 + 8 pad = 1040B stride)
#define XS_BYTES (MM * XROWH * 2)

__device__ __forceinline__ unsigned smem_u32(const void* p) {
    unsigned a;
    asm("{ .reg .u64 t; cvta.to.shared.u64 t, %1; cvt.u32.u64 %0, t; }"
        : "=r"(a) : "l"(p));
    return a;
}
__device__ __forceinline__ void cp_async16(unsigned saddr, const void* gptr) {
    asm volatile("cp.async.cg.shared.global [%0], [%1], 16;\n"
                 :: "r"(saddr), "l"(gptr));
}
__device__ __forceinline__ void cp_commit() {
    asm volatile("cp.async.commit_group;\n" ::: "memory");
}
template <int N>
__device__ __forceinline__ void cp_wait() {
    asm volatile("cp.async.wait_group %0;\n" :: "n"(N) : "memory");
}
__device__ __forceinline__ void ldsm4(unsigned& r0, unsigned& r1,
                                      unsigned& r2, unsigned& r3, unsigned a) {
    asm volatile("ldmatrix.sync.aligned.m8n8.x4.shared.b16 {%0,%1,%2,%3}, [%4];"
                 : "=r"(r0), "=r"(r1), "=r"(r2), "=r"(r3) : "r"(a));
}
__device__ __forceinline__ void mma16816(float d[4], const unsigned a[4],
                                         const unsigned b[2]) {
    asm volatile(
        "mma.sync.aligned.m16n8k16.row.col.f32.f16.f16.f32 "
        "{%0,%1,%2,%3}, {%4,%5,%6,%7}, {%8,%9}, {%0,%1,%2,%3};"
        : "+f"(d[0]), "+f"(d[1]), "+f"(d[2]), "+f"(d[3])
        : "r"(a[0]), "r"(a[1]), "r"(a[2]), "r"(a[3]), "r"(b[0]), "r"(b[1]));
}
__device__ __forceinline__ void red2(float* p, float a, float b) {
    asm volatile("red.global.add.v2.f32 [%0], {%1, %2};"
                 :: "l"(p), "f"(a), "f"(b) : "memory");
}
// raw biased dequant: byte b (2 nibbles) -> fp16x2 {lo = 1024+lo_nib (even k),
// hi = 1024+hi_nib (odd k)}. Exact in fp16 (ulp@1024 = 1). 3 ALU ops.
__device__ __forceinline__ unsigned dqraw(int b) {
    unsigned t = (unsigned)b | ((unsigned)b << 12);
    return (t & 0x000F000Fu) | 0x64006400u;
}

__global__ void __launch_bounds__(NTHREADS)
gptq_init(const float* __restrict__ bias, float* __restrict__ out) {
    int i = blockIdx.x * NTHREADS + threadIdx.x;
    out[i] = bias[i & (NDIM - 1)];
}

extern __shared__ char smem_raw[];

__global__ void __launch_bounds__(NTHREADS, 2)
gptq_main(const float* __restrict__ x, const int* __restrict__ pw,
          const float* __restrict__ scales, const float* __restrict__ zeros,
          float* __restrict__ out)
{
    int* ws = reinterpret_cast<int*>(smem_raw);                        // [2][128][WROW]
    __half* xs = reinterpret_cast<__half*>(smem_raw + WS_BYTES);       // [32][XROWH]
    float* xsum = reinterpret_cast<float*>(smem_raw + WS_BYTES + XS_BYTES); // [8][32]
    float* c1s = xsum + GROUPS_PER * 32;                               // [8][128] s
    float* c2s = c1s + GROUPS_PER * NBLK;                              // [8][128] s*(z+1024)

    const int tid = threadIdx.x;
    const int w = tid >> 5;
    const int l = tid & 31;
    const int nblock0 = blockIdx.x * NBLK;
    const int k0 = blockIdx.y * KPER;
    const int g0 = blockIdx.y * GROUPS_PER;

    const unsigned ws_base = smem_u32(ws);
    const int s_chunk = tid & 7;
    const int s_row0  = tid >> 3;

    auto stage_w = [&](int g, int b) {
        const int* gsrc = pw + ((k0 + g * GS) >> 1) + s_chunk * 4;
        unsigned sdst = ws_base + (unsigned)(b * WBUF + s_row0 * WROW + s_chunk * 4) * 4u;
#pragma unroll
        for (int i = 0; i < 4; ++i)
            cp_async16(sdst + (unsigned)(i * 32 * WROW) * 4u,
                       gsrc + (size_t)(nblock0 + s_row0 + i * 32) * (KDIM / 2));
        cp_commit();
    };
    stage_w(0, 0);
    stage_w(1, 1);

    // zero X LUT, barrier before atomic accumulation
    xsum[tid] = 0.0f;
    __syncthreads();

    // ---- stage x: fp32 -> fp16 smem + accumulate X_g[m] = sum fp16(x) ----
    {
        unsigned* xsu = reinterpret_cast<unsigned*>(xs);
#pragma unroll
        for (int i = 0; i < 16; ++i) {
            int lin = tid + i * NTHREADS;  // 0..4095 float4s
            int v = lin & 127;             // float4 index along k (group = v>>4)
            int m = lin >> 7;
            float4 xv = *reinterpret_cast<const float4*>(x + (size_t)m * KDIM + k0 + 4 * v);
            __half2 h0 = __floats2half2_rn(xv.x, xv.y);
            __half2 h1 = __floats2half2_rn(xv.z, xv.w);
            int idx = m * (XROWH / 2) + v * 2;
            xsu[idx]     = *reinterpret_cast<unsigned*>(&h0);
            xsu[idx + 1] = *reinterpret_cast<unsigned*>(&h1);
            float2 f0 = __half22float2(h0);
            float2 f1 = __half22float2(h1);
            atomicAdd(&xsum[(v >> 4) * 32 + m], (f0.x + f0.y) + (f1.x + f1.y));
        }
    }

    // ---- fill scale/zero LUT: c1[g][n] = s, c2[g][n] = s*(z+1024), coalesced ----
#pragma unroll
    for (int i = 0; i < 4; ++i) {
        int lin = tid + i * NTHREADS;   // 0..1023
        int g = lin & 7;
        int n = lin >> 3;               // 0..127
        float s = __ldg(scales + (size_t)(nblock0 + n) * NGROUPS + g0 + g);
        float z = __ldg(zeros  + (size_t)(nblock0 + n) * NGROUPS + g0 + g);
        c1s[g * NBLK + n] = s;
        c2s[g * NBLK + n] = s * (z + 1024.0f);
    }

    // A-fragment ldmatrix lane addresses
    const unsigned xs_base = smem_u32(xs);
    const unsigned xa0 = xs_base + (unsigned)((l & 15) * XROWH * 2) + (unsigned)((l >> 4) * 16);
    const unsigned xa1 = xa0 + 16u * XROWH * 2;

    // weight smem indices (B-frag n = l>>2, k-pairs l&3 and (l&3)+4)
    const int wr0 = (w * 16 + 0 + (l >> 2)) * WROW + (l & 3);
    const int wr1 = (w * 16 + 8 + (l >> 2)) * WROW + (l & 3);

    // accumulator column base within CTA: n_local = w*16 + tn*8 + 2*(l&3) + c
    const int ncol = w * 16 + 2 * (l & 3);

    float acc[2][2][4] = {};   // final [m-tile][n-tile][frag]

#pragma unroll
    for (int g = 0; g < GROUPS_PER; ++g) {
        if (g == GROUPS_PER - 1) cp_wait<0>(); else cp_wait<1>();
        __syncthreads();

        const int bufo = (g & 1) * WBUF;
        float accg[2][2][4] = {};   // group-local biased accumulators

#pragma unroll
        for (int s4 = 0; s4 < 4; ++s4) {
            const int s = g * 4 + s4;
            unsigned a0[4], a1[4];
            ldsm4(a0[0], a0[1], a0[2], a0[3], xa0 + s * 32);
            ldsm4(a1[0], a1[1], a1[2], a1[3], xa1 + s * 32);

            unsigned b0[2], b1[2];
            b0[0] = dqraw(ws[bufo + wr0 + s4 * 8]);
            b0[1] = dqraw(ws[bufo + wr0 + s4 * 8 + 4]);
            b1[0] = dqraw(ws[bufo + wr1 + s4 * 8]);
            b1[1] = dqraw(ws[bufo + wr1 + s4 * 8 + 4]);

            mma16816(accg[0][0], a0, b0);
            mma16816(accg[0][1], a0, b1);
            mma16816(accg[1][0], a1, b0);
            mma16816(accg[1][1], a1, b1);
        }

        // per-group fixup at the accumulator's true columns:
        // acc[tm][tn][e] += s[tn][e&1]*accg[tm][tn][e] - c2[tn][e&1]*X_g[row]
        {
            const float* xg = xsum + g * 32 + (l >> 2);
            float Xv[4];
            Xv[0] = xg[0];  Xv[1] = xg[8];   // m-tile 0: rows r, r+8
            Xv[2] = xg[16]; Xv[3] = xg[24];  // m-tile 1
            const float* c1g = c1s + g * NBLK + ncol;
            const float* c2g = c2s + g * NBLK + ncol;
            float s00 = c1g[0], s01 = c1g[1], s10 = c1g[8], s11 = c1g[9];
            float t00 = c2g[0], t01 = c2g[1], t10 = c2g[8], t11 = c2g[9];
#pragma unroll
            for (int tm = 0; tm < 2; ++tm) {
#pragma unroll
                for (int e = 0; e < 4; ++e) {
                    const float Xe = Xv[tm * 2 + (e >> 1)];
                    const float se0 = (e & 1) ? s01 : s00;
                    const float te0 = (e & 1) ? t01 : t00;
                    const float se1 = (e & 1) ? s11 : s10;
                    const float te1 = (e & 1) ? t11 : t10;
                    acc[tm][0][e] = fmaf(se0, accg[tm][0][e],
                                         fmaf(-te0, Xe, acc[tm][0][e]));
                    acc[tm][1][e] = fmaf(se1, accg[tm][1][e],
                                         fmaf(-te1, Xe, acc[tm][1][e]));
                }
            }
        }

        if (g < GROUPS_PER - 2) {
            __syncthreads();           // all warps done reading buffer g&1
            stage_w(g + 2, g & 1);
        }
    }

    // ---- epilogue: K-split partials via vector reductions ----
#pragma unroll
    for (int tm = 0; tm < 2; ++tm) {
#pragma unroll
        for (int tn = 0; tn < 2; ++tn) {
            const int n = nblock0 + w * 16 + tn * 8 + (l & 3) * 2;
            const int m = tm * 16 + (l >> 2);
            red2(out + (size_t)m * NDIM + n,       acc[tm][tn][0], acc[tm][tn][1]);
            red2(out + (size_t)(m + 8) * NDIM + n, acc[tm][tn][2], acc[tm][tn][3]);
        }
    }
}

extern "C" void kernel_launch(void* const* d_in, const int* in_sizes, int n_in,
                              void* d_out, int out_size) {
    const float* x      = (const float*)d_in[0];
    const int*   pw     = (const int*)d_in[1];
    const float* scales = (const float*)d_in[2];
    const float* zeros  = (const float*)d_in[3];
    const float* bias   = (const float*)d_in[4];
    float* out = (float*)d_out;

    gptq_init<<<(MM * NDIM) / NTHREADS, NTHREADS>>>(bias, out);

    size_t smem = WS_BYTES + XS_BYTES +
                  (GROUPS_PER * 32 + 2 * GROUPS_PER * NBLK) * sizeof(float); // 79360
    cudaFuncSetAttribute(gptq_main, cudaFuncAttributeMaxDynamicSharedMemorySize, (int)smem);

    dim3 grid(NDIM / NBLK, KSPLIT);
    gptq_main<<<grid, NTHREADS, smem>>>(x, pw, scales, zeros, out);
}

// round 9
// speedup vs baseline: 1.0121x; 1.0121x over previous
#include <cuda_runtime.h>
#include <cuda_fp16.h>

// GPTQ int4 dequant GEMM via HMMA: out[32,8192] = x @ dequant(W)^T + bias
// M=32, K=8192, N=8192, group=64. packed int32 element = one byte = 2 k-nibbles.
// v9: MMA on raw biased nibbles (1024+q, exact fp16, 3 ALU ops/byte) accumulating
// DIRECTLY into the one fp32 accumulator; per-group running rescale
//   acc = (acc - (z_g+1024)*X_g[row]) * (s_g/s_{g+1})   (last ratio = s_last)
// telescopes to sum_g s_g*(P_g - (z+1024)X_g). No second accumulator array ->
// no spill (v8's failure). v5's proven 2-deep cp.async ring. red.v2 epilogue.

#define MM 32
#define KDIM 8192
#define NDIM 8192
#define GS 64
#define NGROUPS 128
#define NTHREADS 256
#define NBLK 128           // n per CTA
#define KSPLIT 16
#define KPER 512           // k per CTA
#define GROUPS_PER 8       // KPER / GS
#define WROW 36            // int32 per ws row (32 data + 4 pad = 144B stride)
#define WBUF (NBLK * WROW) // int32 per ring buffer (one group)
#define WS_BYTES (2 * WBUF * 4)
#define XROWH 520          // halfs per xs row (512 + 8 pad = 1040B stride)
#define XS_BYTES (MM * XROWH * 2)

__device__ __forceinline__ unsigned smem_u32(const void* p) {
    unsigned a;
    asm("{ .reg .u64 t; cvta.to.shared.u64 t, %1; cvt.u32.u64 %0, t; }"
        : "=r"(a) : "l"(p));
    return a;
}
__device__ __forceinline__ void cp_async16(unsigned saddr, const void* gptr) {
    asm volatile("cp.async.cg.shared.global [%0], [%1], 16;\n"
                 :: "r"(saddr), "l"(gptr));
}
__device__ __forceinline__ void cp_commit() {
    asm volatile("cp.async.commit_group;\n" ::: "memory");
}
template <int N>
__device__ __forceinline__ void cp_wait() {
    asm volatile("cp.async.wait_group %0;\n" :: "n"(N) : "memory");
}
__device__ __forceinline__ void ldsm4(unsigned& r0, unsigned& r1,
                                      unsigned& r2, unsigned& r3, unsigned a) {
    asm volatile("ldmatrix.sync.aligned.m8n8.x4.shared.b16 {%0,%1,%2,%3}, [%4];"
                 : "=r"(r0), "=r"(r1), "=r"(r2), "=r"(r3) : "r"(a));
}
__device__ __forceinline__ void mma16816(float d[4], const unsigned a[4],
                                         const unsigned b[2]) {
    asm volatile(
        "mma.sync.aligned.m16n8k16.row.col.f32.f16.f16.f32 "
        "{%0,%1,%2,%3}, {%4,%5,%6,%7}, {%8,%9}, {%0,%1,%2,%3};"
        : "+f"(d[0]), "+f"(d[1]), "+f"(d[2]), "+f"(d[3])
        : "r"(a[0]), "r"(a[1]), "r"(a[2]), "r"(a[3]), "r"(b[0]), "r"(b[1]));
}
__device__ __forceinline__ void red2(float* p, float a, float b) {
    asm volatile("red.global.add.v2.f32 [%0], {%1, %2};"
                 :: "l"(p), "f"(a), "f"(b) : "memory");
}
// raw biased dequant: byte b (2 nibbles) -> fp16x2 {lo = 1024+lo_nib (even k),
// hi = 1024+hi_nib (odd k)}. Exact in fp16. 3 ALU ops.
__device__ __forceinline__ unsigned dqraw(int b) {
    unsigned t = (unsigned)b | ((unsigned)b << 12);
    return (t & 0x000F000Fu) | 0x64006400u;
}

__global__ void __launch_bounds__(NTHREADS)
gptq_init(const float* __restrict__ bias, float* __restrict__ out) {
    int i = blockIdx.x * NTHREADS + threadIdx.x;
    out[i] = bias[i & (NDIM - 1)];
}

extern __shared__ char smem_raw[];

__global__ void __launch_bounds__(NTHREADS, 2)
gptq_main(const float* __restrict__ x, const int* __restrict__ pw,
          const float* __restrict__ scales, const float* __restrict__ zeros,
          float* __restrict__ out)
{
    int* ws = reinterpret_cast<int*>(smem_raw);                        // [2][128][WROW]
    __half* xs = reinterpret_cast<__half*>(smem_raw + WS_BYTES);       // [32][XROWH]
    float* xsum = reinterpret_cast<float*>(smem_raw + WS_BYTES + XS_BYTES); // [8][32]
    float* c2s = xsum + GROUPS_PER * 32;                               // [8][128] z+1024
    float* rqs = c2s + GROUPS_PER * NBLK;                              // [8][128] ratio

    const int tid = threadIdx.x;
    const int w = tid >> 5;
    const int l = tid & 31;
    const int nblock0 = blockIdx.x * NBLK;
    const int k0 = blockIdx.y * KPER;
    const int g0 = blockIdx.y * GROUPS_PER;

    const unsigned ws_base = smem_u32(ws);
    const int s_chunk = tid & 7;
    const int s_row0  = tid >> 3;

    auto stage_w = [&](int g, int b) {
        const int* gsrc = pw + ((k0 + g * GS) >> 1) + s_chunk * 4;
        unsigned sdst = ws_base + (unsigned)(b * WBUF + s_row0 * WROW + s_chunk * 4) * 4u;
#pragma unroll
        for (int i = 0; i < 4; ++i)
            cp_async16(sdst + (unsigned)(i * 32 * WROW) * 4u,
                       gsrc + (size_t)(nblock0 + s_row0 + i * 32) * (KDIM / 2));
        cp_commit();
    };
    stage_w(0, 0);
    stage_w(1, 1);

    // zero X LUT, barrier before atomic accumulation
    xsum[tid] = 0.0f;
    __syncthreads();

    // ---- stage x: fp32 -> fp16 smem + accumulate X_g[m] = sum fp16(x) ----
    {
        unsigned* xsu = reinterpret_cast<unsigned*>(xs);
#pragma unroll
        for (int i = 0; i < 16; ++i) {
            int lin = tid + i * NTHREADS;  // 0..4095 float4s
            int v = lin & 127;             // float4 index along k (group = v>>4)
            int m = lin >> 7;
            float4 xv = *reinterpret_cast<const float4*>(x + (size_t)m * KDIM + k0 + 4 * v);
            __half2 h0 = __floats2half2_rn(xv.x, xv.y);
            __half2 h1 = __floats2half2_rn(xv.z, xv.w);
            int idx = m * (XROWH / 2) + v * 2;
            xsu[idx]     = *reinterpret_cast<unsigned*>(&h0);
            xsu[idx + 1] = *reinterpret_cast<unsigned*>(&h1);
            float2 f0 = __half22float2(h0);
            float2 f1 = __half22float2(h1);
            atomicAdd(&xsum[(v >> 4) * 32 + m], (f0.x + f0.y) + (f1.x + f1.y));
        }
    }

    // ---- fill LUTs: c2[g][n] = z+1024; rq[g][n] = s_g/s_{g+1} (g<7), s_7 (g==7) ----
#pragma unroll
    for (int i = 0; i < 4; ++i) {
        int lin = tid + i * NTHREADS;   // 0..1023
        int g = lin & 7;
        int n = lin >> 3;               // 0..127
        const float* srow = scales + (size_t)(nblock0 + n) * NGROUPS + g0;
        float s = __ldg(srow + g);
        float z = __ldg(zeros + (size_t)(nblock0 + n) * NGROUPS + g0 + g);
        float rq;
        if (g < GROUPS_PER - 1) {
            float sn = __ldg(srow + g + 1);
            rq = __fdividef(s, sn);
        } else {
            rq = s;                     // last group: convert T to output units
        }
        c2s[g * NBLK + n] = z + 1024.0f;
        rqs[g * NBLK + n] = rq;
    }

    // A-fragment ldmatrix lane addresses
    const unsigned xs_base = smem_u32(xs);
    const unsigned xa0 = xs_base + (unsigned)((l & 15) * XROWH * 2) + (unsigned)((l >> 4) * 16);
    const unsigned xa1 = xa0 + 16u * XROWH * 2;

    // weight smem indices (B-frag n = l>>2, k-pairs l&3 and (l&3)+4)
    const int wr0 = (w * 16 + 0 + (l >> 2)) * WROW + (l & 3);
    const int wr1 = (w * 16 + 8 + (l >> 2)) * WROW + (l & 3);

    // accumulator column base within CTA: n_local = w*16 + tn*8 + 2*(l&3) + (e&1)
    const int ncol = w * 16 + 2 * (l & 3);

    float acc[2][2][4] = {};   // [m-tile][n-tile][frag] in running s_g units

#pragma unroll
    for (int g = 0; g < GROUPS_PER; ++g) {
        if (g == GROUPS_PER - 1) cp_wait<0>(); else cp_wait<1>();
        __syncthreads();

        const int bufo = (g & 1) * WBUF;

#pragma unroll
        for (int s4 = 0; s4 < 4; ++s4) {
            const int s = g * 4 + s4;
            unsigned a0[4], a1[4];
            ldsm4(a0[0], a0[1], a0[2], a0[3], xa0 + s * 32);
            ldsm4(a1[0], a1[1], a1[2], a1[3], xa1 + s * 32);

            unsigned b0[2], b1[2];
            b0[0] = dqraw(ws[bufo + wr0 + s4 * 8]);
            b0[1] = dqraw(ws[bufo + wr0 + s4 * 8 + 4]);
            b1[0] = dqraw(ws[bufo + wr1 + s4 * 8]);
            b1[1] = dqraw(ws[bufo + wr1 + s4 * 8 + 4]);

            mma16816(acc[0][0], a0, b0);
            mma16816(acc[0][1], a0, b1);
            mma16816(acc[1][0], a1, b0);
            mma16816(acc[1][1], a1, b1);
        }

        // end-of-group: acc = (acc - (z+1024)*X_g[row]) * rq  (column-correct LUTs)
        {
            const float* xg = xsum + g * 32 + (l >> 2);
            float Xv[4];
            Xv[0] = xg[0];  Xv[1] = xg[8];   // m-tile 0: rows r, r+8
            Xv[2] = xg[16]; Xv[3] = xg[24];  // m-tile 1
            const float* c2g = c2s + g * NBLK + ncol;
            const float* rqg = rqs + g * NBLK + ncol;
            float c2v[4], rqv[4];
            c2v[0] = c2g[0]; c2v[1] = c2g[1]; c2v[2] = c2g[8]; c2v[3] = c2g[9];
            rqv[0] = rqg[0]; rqv[1] = rqg[1]; rqv[2] = rqg[8]; rqv[3] = rqg[9];
#pragma unroll
            for (int tm = 0; tm < 2; ++tm)
#pragma unroll
                for (int tn = 0; tn < 2; ++tn)
#pragma unroll
                    for (int e = 0; e < 4; ++e) {
                        const float Xe = Xv[tm * 2 + (e >> 1)];
                        const float c2e = c2v[tn * 2 + (e & 1)];
                        const float rqe = rqv[tn * 2 + (e & 1)];
                        acc[tm][tn][e] = fmaf(-c2e, Xe, acc[tm][tn][e]) * rqe;
                    }
        }

        if (g < GROUPS_PER - 2) {
            __syncthreads();           // all warps done reading buffer g&1
            stage_w(g + 2, g & 1);
        }
    }

    // ---- epilogue: K-split partials via vector reductions (already scaled) ----
#pragma unroll
    for (int tm = 0; tm < 2; ++tm) {
#pragma unroll
        for (int tn = 0; tn < 2; ++tn) {
            const int n = nblock0 + w * 16 + tn * 8 + (l & 3) * 2;
            const int m = tm * 16 + (l >> 2);
            red2(out + (size_t)m * NDIM + n,       acc[tm][tn][0], acc[tm][tn][1]);
            red2(out + (size_t)(m + 8) * NDIM + n, acc[tm][tn][2], acc[tm][tn][3]);
        }
    }
}

extern "C" void kernel_launch(void* const* d_in, const int* in_sizes, int n_in,
                              void* d_out, int out_size) {
    const float* x      = (const float*)d_in[0];
    const int*   pw     = (const int*)d_in[1];
    const float* scales = (const float*)d_in[2];
    const float* zeros  = (const float*)d_in[3];
    const float* bias   = (const float*)d_in[4];
    float* out = (float*)d_out;

    gptq_init<<<(MM * NDIM) / NTHREADS, NTHREADS>>>(bias, out);

    size_t smem = WS_BYTES + XS_BYTES +
                  (GROUPS_PER * 32 + 2 * GROUPS_PER * NBLK) * sizeof(float); // 79360
    cudaFuncSetAttribute(gptq_main, cudaFuncAttributeMaxDynamicSharedMemorySize, (int)smem);

    dim3 grid(NDIM / NBLK, KSPLIT);
    gptq_main<<<grid, NTHREADS, smem>>>(x, pw, scales, zeros, out);
}

// round 10
// speedup vs baseline: 2.4588x; 2.4295x over previous
#include <cuda_runtime.h>
#include <cuda_fp16.h>

// GPTQ int4 dequant GEMM via HMMA: out[32,8192] = x @ dequant(W)^T + bias
// M=32, K=8192, N=8192, group=64. packed int32 element = one byte = 2 k-nibbles.
// v10: v9's lean mainloop (MMA on raw biased nibbles 1024+q, 3 ALU ops/byte;
// per-group running rescale acc=(acc-(z+1024)*X)*s_g/s_{g+1}) but X_g[m] is now
// computed ONCE by a tiny pre-kernel into a global LUT (v8/v9's per-CTA smem
// atomicAdd storm doubled L1 work and caused the 110us regression).
// v5's proven 2-deep cp.async ring. red.v2 K-split epilogue.

#define MM 32
#define KDIM 8192
#define NDIM 8192
#define GS 64
#define NGROUPS 128
#define NTHREADS 256
#define NBLK 128           // n per CTA
#define KSPLIT 16
#define KPER 512           // k per CTA
#define GROUPS_PER 8       // KPER / GS
#define WROW 36            // int32 per ws row (32 data + 4 pad = 144B stride)
#define WBUF (NBLK * WROW) // int32 per ring buffer (one group)
#define WS_BYTES (2 * WBUF * 4)
#define XROWH 520          // halfs per xs row (512 + 8 pad = 1040B stride)
#define XS_BYTES (MM * XROWH * 2)

// global LUT: X_g[m] = sum_{k in group g} fp16(x[m,k]), fp32. 16 KB.
__device__ float d_Xg[NGROUPS * MM];

__device__ __forceinline__ unsigned smem_u32(const void* p) {
    unsigned a;
    asm("{ .reg .u64 t; cvta.to.shared.u64 t, %1; cvt.u32.u64 %0, t; }"
        : "=r"(a) : "l"(p));
    return a;
}
__device__ __forceinline__ void cp_async16(unsigned saddr, const void* gptr) {
    asm volatile("cp.async.cg.shared.global [%0], [%1], 16;\n"
                 :: "r"(saddr), "l"(gptr));
}
__device__ __forceinline__ void cp_commit() {
    asm volatile("cp.async.commit_group;\n" ::: "memory");
}
template <int N>
__device__ __forceinline__ void cp_wait() {
    asm volatile("cp.async.wait_group %0;\n" :: "n"(N) : "memory");
}
__device__ __forceinline__ void ldsm4(unsigned& r0, unsigned& r1,
                                      unsigned& r2, unsigned& r3, unsigned a) {
    asm volatile("ldmatrix.sync.aligned.m8n8.x4.shared.b16 {%0,%1,%2,%3}, [%4];"
                 : "=r"(r0), "=r"(r1), "=r"(r2), "=r"(r3) : "r"(a));
}
__device__ __forceinline__ void mma16816(float d[4], const unsigned a[4],
                                         const unsigned b[2]) {
    asm volatile(
        "mma.sync.aligned.m16n8k16.row.col.f32.f16.f16.f32 "
        "{%0,%1,%2,%3}, {%4,%5,%6,%7}, {%8,%9}, {%0,%1,%2,%3};"
        : "+f"(d[0]), "+f"(d[1]), "+f"(d[2]), "+f"(d[3])
        : "r"(a[0]), "r"(a[1]), "r"(a[2]), "r"(a[3]), "r"(b[0]), "r"(b[1]));
}
__device__ __forceinline__ void red2(float* p, float a, float b) {
    asm volatile("red.global.add.v2.f32 [%0], {%1, %2};"
                 :: "l"(p), "f"(a), "f"(b) : "memory");
}
// raw biased dequant: byte b (2 nibbles) -> fp16x2 {lo = 1024+lo_nib (even k),
// hi = 1024+hi_nib (odd k)}. Exact in fp16. 3 ALU ops.
__device__ __forceinline__ unsigned dqraw(int b) {
    unsigned t = (unsigned)b | ((unsigned)b << 12);
    return (t & 0x000F000Fu) | 0x64006400u;
}

__global__ void __launch_bounds__(NTHREADS)
gptq_init(const float* __restrict__ bias, float* __restrict__ out) {
    int i = blockIdx.x * NTHREADS + threadIdx.x;
    out[i] = bias[i & (NDIM - 1)];
}

// pre-kernel: X_g[m] for all 128 groups x 32 m. grid=32 (one block per m).
// thread t handles float4 indices f = t + 256*i (i<8); group(f) = (t>>4) + 16*i,
// so the 16 threads sharing t>>4 reduce via shfl over their 8 per-i partials.
__global__ void __launch_bounds__(NTHREADS)
gptq_xsums(const float* __restrict__ x) {
    const int m = blockIdx.x;
    const int t = threadIdx.x;
    const int l = t & 31;
    const float4* xr = reinterpret_cast<const float4*>(x + (size_t)m * KDIM);
    float s[8];
#pragma unroll
    for (int i = 0; i < 8; ++i) {
        float4 v = xr[t + 256 * i];
        __half2 h0 = __floats2half2_rn(v.x, v.y);
        __half2 h1 = __floats2half2_rn(v.z, v.w);
        float2 f0 = __half22float2(h0);
        float2 f1 = __half22float2(h1);
        s[i] = (f0.x + f0.y) + (f1.x + f1.y);
    }
#pragma unroll
    for (int mask = 1; mask < 16; mask <<= 1)
#pragma unroll
        for (int i = 0; i < 8; ++i)
            s[i] += __shfl_xor_sync(0xFFFFFFFFu, s[i], mask);
    const int j = l & 15;            // lane within 16-thread cluster
    if (j < 8) {
        const int g = (t >> 4) + 16 * j;
        d_Xg[g * MM + m] = s[j];
    }
}

extern __shared__ char smem_raw[];

__global__ void __launch_bounds__(NTHREADS, 2)
gptq_main(const float* __restrict__ x, const int* __restrict__ pw,
          const float* __restrict__ scales, const float* __restrict__ zeros,
          float* __restrict__ out)
{
    int* ws = reinterpret_cast<int*>(smem_raw);                        // [2][128][WROW]
    __half* xs = reinterpret_cast<__half*>(smem_raw + WS_BYTES);       // [32][XROWH]
    float* xsum = reinterpret_cast<float*>(smem_raw + WS_BYTES + XS_BYTES); // [8][32]
    float* c2s = xsum + GROUPS_PER * 32;                               // [8][128] z+1024
    float* rqs = c2s + GROUPS_PER * NBLK;                              // [8][128] ratio

    const int tid = threadIdx.x;
    const int w = tid >> 5;
    const int l = tid & 31;
    const int nblock0 = blockIdx.x * NBLK;
    const int k0 = blockIdx.y * KPER;
    const int g0 = blockIdx.y * GROUPS_PER;

    const unsigned ws_base = smem_u32(ws);
    const int s_chunk = tid & 7;
    const int s_row0  = tid >> 3;

    auto stage_w = [&](int g, int b) {
        const int* gsrc = pw + ((k0 + g * GS) >> 1) + s_chunk * 4;
        unsigned sdst = ws_base + (unsigned)(b * WBUF + s_row0 * WROW + s_chunk * 4) * 4u;
#pragma unroll
        for (int i = 0; i < 4; ++i)
            cp_async16(sdst + (unsigned)(i * 32 * WROW) * 4u,
                       gsrc + (size_t)(nblock0 + s_row0 + i * 32) * (KDIM / 2));
        cp_commit();
    };
    stage_w(0, 0);
    stage_w(1, 1);

    // ---- stage x: fp32 -> fp16 smem (v5 pattern, no atomics) ----
    {
        unsigned* xsu = reinterpret_cast<unsigned*>(xs);
#pragma unroll
        for (int i = 0; i < 16; ++i) {
            int lin = tid + i * NTHREADS;  // 0..4095 float4s
            int v = lin & 127;
            int m = lin >> 7;
            float4 xv = *reinterpret_cast<const float4*>(x + (size_t)m * KDIM + k0 + 4 * v);
            __half2 h0 = __floats2half2_rn(xv.x, xv.y);
            __half2 h1 = __floats2half2_rn(xv.z, xv.w);
            int idx = m * (XROWH / 2) + v * 2;
            xsu[idx]     = *reinterpret_cast<unsigned*>(&h0);
            xsu[idx + 1] = *reinterpret_cast<unsigned*>(&h1);
        }
    }

    // ---- X LUT slice: one coalesced LDG per thread ----
    xsum[tid] = __ldg(&d_Xg[(g0 + (tid >> 5)) * MM + (tid & 31)]);

    // ---- fill LUTs: c2[g][n] = z+1024; rq[g][n] = s_g/s_{g+1} (g<7), s_7 (g==7) ----
#pragma unroll
    for (int i = 0; i < 4; ++i) {
        int lin = tid + i * NTHREADS;   // 0..1023
        int g = lin & 7;
        int n = lin >> 3;               // 0..127
        const float* srow = scales + (size_t)(nblock0 + n) * NGROUPS + g0;
        float s = __ldg(srow + g);
        float z = __ldg(zeros + (size_t)(nblock0 + n) * NGROUPS + g0 + g);
        float rq;
        if (g < GROUPS_PER - 1) {
            float sn = __ldg(srow + g + 1);
            rq = __fdividef(s, sn);
        } else {
            rq = s;                     // last group: convert to output units
        }
        c2s[g * NBLK + n] = z + 1024.0f;
        rqs[g * NBLK + n] = rq;
    }

    // A-fragment ldmatrix lane addresses
    const unsigned xs_base = smem_u32(xs);
    const unsigned xa0 = xs_base + (unsigned)((l & 15) * XROWH * 2) + (unsigned)((l >> 4) * 16);
    const unsigned xa1 = xa0 + 16u * XROWH * 2;

    // weight smem indices (B-frag n = l>>2, k-pairs l&3 and (l&3)+4)
    const int wr0 = (w * 16 + 0 + (l >> 2)) * WROW + (l & 3);
    const int wr1 = (w * 16 + 8 + (l >> 2)) * WROW + (l & 3);

    // accumulator column base within CTA: n_local = w*16 + tn*8 + 2*(l&3) + (e&1)
    const int ncol = w * 16 + 2 * (l & 3);

    float acc[2][2][4] = {};   // [m-tile][n-tile][frag] in running s_g units

#pragma unroll
    for (int g = 0; g < GROUPS_PER; ++g) {
        if (g == GROUPS_PER - 1) cp_wait<0>(); else cp_wait<1>();
        __syncthreads();

        const int bufo = (g & 1) * WBUF;

#pragma unroll
        for (int s4 = 0; s4 < 4; ++s4) {
            const int s = g * 4 + s4;
            unsigned a0[4], a1[4];
            ldsm4(a0[0], a0[1], a0[2], a0[3], xa0 + s * 32);
            ldsm4(a1[0], a1[1], a1[2], a1[3], xa1 + s * 32);

            unsigned b0[2], b1[2];
            b0[0] = dqraw(ws[bufo + wr0 + s4 * 8]);
            b0[1] = dqraw(ws[bufo + wr0 + s4 * 8 + 4]);
            b1[0] = dqraw(ws[bufo + wr1 + s4 * 8]);
            b1[1] = dqraw(ws[bufo + wr1 + s4 * 8 + 4]);

            mma16816(acc[0][0], a0, b0);
            mma16816(acc[0][1], a0, b1);
            mma16816(acc[1][0], a1, b0);
            mma16816(acc[1][1], a1, b1);
        }

        // end-of-group: acc = (acc - (z+1024)*X_g[row]) * rq  (column-correct LUTs)
        {
            const float* xg = xsum + g * 32 + (l >> 2);
            float Xv[4];
            Xv[0] = xg[0];  Xv[1] = xg[8];   // m-tile 0: rows r, r+8
            Xv[2] = xg[16]; Xv[3] = xg[24];  // m-tile 1
            const float* c2g = c2s + g * NBLK + ncol;
            const float* rqg = rqs + g * NBLK + ncol;
            float c2v[4], rqv[4];
            c2v[0] = c2g[0]; c2v[1] = c2g[1]; c2v[2] = c2g[8]; c2v[3] = c2g[9];
            rqv[0] = rqg[0]; rqv[1] = rqg[1]; rqv[2] = rqg[8]; rqv[3] = rqg[9];
#pragma unroll
            for (int tm = 0; tm < 2; ++tm)
#pragma unroll
                for (int tn = 0; tn < 2; ++tn)
#pragma unroll
                    for (int e = 0; e < 4; ++e) {
                        const float Xe = Xv[tm * 2 + (e >> 1)];
                        const float c2e = c2v[tn * 2 + (e & 1)];
                        const float rqe = rqv[tn * 2 + (e & 1)];
                        acc[tm][tn][e] = fmaf(-c2e, Xe, acc[tm][tn][e]) * rqe;
                    }
        }

        if (g < GROUPS_PER - 2) {
            __syncthreads();           // all warps done reading buffer g&1
            stage_w(g + 2, g & 1);
        }
    }

    // ---- epilogue: K-split partials via vector reductions (already scaled) ----
#pragma unroll
    for (int tm = 0; tm < 2; ++tm) {
#pragma unroll
        for (int tn = 0; tn < 2; ++tn) {
            const int n = nblock0 + w * 16 + tn * 8 + (l & 3) * 2;
            const int m = tm * 16 + (l >> 2);
            red2(out + (size_t)m * NDIM + n,       acc[tm][tn][0], acc[tm][tn][1]);
            red2(out + (size_t)(m + 8) * NDIM + n, acc[tm][tn][2], acc[tm][tn][3]);
        }
    }
}

extern "C" void kernel_launch(void* const* d_in, const int* in_sizes, int n_in,
                              void* d_out, int out_size) {
    const float* x      = (const float*)d_in[0];
    const int*   pw     = (const int*)d_in[1];
    const float* scales = (const float*)d_in[2];
    const float* zeros  = (const float*)d_in[3];
    const float* bias   = (const float*)d_in[4];
    float* out = (float*)d_out;

    gptq_init<<<(MM * NDIM) / NTHREADS, NTHREADS>>>(bias, out);
    gptq_xsums<<<MM, NTHREADS>>>(x);

    size_t smem = WS_BYTES + XS_BYTES +
                  (GROUPS_PER * 32 + 2 * GROUPS_PER * NBLK) * sizeof(float); // 79360
    cudaFuncSetAttribute(gptq_main, cudaFuncAttributeMaxDynamicSharedMemorySize, (int)smem);

    dim3 grid(NDIM / NBLK, KSPLIT);
    gptq_main<<<grid, NTHREADS, smem>>>(x, pw, scales, zeros, out);
}

// round 11
// speedup vs baseline: 2.7168x; 1.1049x over previous
#include <cuda_runtime.h>
#include <cuda_fp16.h>

// GPTQ int4 dequant GEMM via HMMA: out[32,8192] = x @ dequant(W)^T + bias
// M=32, K=8192, N=8192, group=64. packed int32 element = one byte = 2 k-nibbles.
// v11: v10 mainloop (raw biased nibbles 1024+q, running rescale fixup) with ALL
// smem padding replaced by XOR swizzle (chunk16 ^= row&7) -> 74.75KB/CTA ->
// 3 CTAs/SM (24 warps, +50% latency hiding). init+xsums merged into one launch.

#define MM 32
#define KDIM 8192
#define NDIM 8192
#define GS 64
#define NGROUPS 128
#define NTHREADS 256
#define NBLK 128           // n per CTA
#define KSPLIT 16
#define KPER 512           // k per CTA
#define GROUPS_PER 8       // KPER / GS
#define WBUF 4096          // int32 per ring buffer: 128 rows * 32 int32 (no pad)
#define WS_BYTES (2 * WBUF * 4)          // 32768
#define XS_BYTES (MM * 1024)             // 32768 (32 rows * 1024B, no pad)
#define SMEM_TOTAL (WS_BYTES + XS_BYTES + 1024 + 2 * GROUPS_PER * NBLK * 4) // 74752

// global LUT: X_g[m] = sum_{k in group g} fp16(x[m,k]), fp32. 16 KB.
__device__ float d_Xg[NGROUPS * MM];

__device__ __forceinline__ unsigned smem_u32(const void* p) {
    unsigned a;
    asm("{ .reg .u64 t; cvta.to.shared.u64 t, %1; cvt.u32.u64 %0, t; }"
        : "=r"(a) : "l"(p));
    return a;
}
__device__ __forceinline__ void cp_async16(unsigned saddr, const void* gptr) {
    asm volatile("cp.async.cg.shared.global [%0], [%1], 16;\n"
                 :: "r"(saddr), "l"(gptr));
}
__device__ __forceinline__ void cp_commit() {
    asm volatile("cp.async.commit_group;\n" ::: "memory");
}
template <int N>
__device__ __forceinline__ void cp_wait() {
    asm volatile("cp.async.wait_group %0;\n" :: "n"(N) : "memory");
}
__device__ __forceinline__ void ldsm4(unsigned& r0, unsigned& r1,
                                      unsigned& r2, unsigned& r3, unsigned a) {
    asm volatile("ldmatrix.sync.aligned.m8n8.x4.shared.b16 {%0,%1,%2,%3}, [%4];"
                 : "=r"(r0), "=r"(r1), "=r"(r2), "=r"(r3) : "r"(a));
}
__device__ __forceinline__ void mma16816(float d[4], const unsigned a[4],
                                         const unsigned b[2]) {
    asm volatile(
        "mma.sync.aligned.m16n8k16.row.col.f32.f16.f16.f32 "
        "{%0,%1,%2,%3}, {%4,%5,%6,%7}, {%8,%9}, {%0,%1,%2,%3};"
        : "+f"(d[0]), "+f"(d[1]), "+f"(d[2]), "+f"(d[3])
        : "r"(a[0]), "r"(a[1]), "r"(a[2]), "r"(a[3]), "r"(b[0]), "r"(b[1]));
}
__device__ __forceinline__ void red2(float* p, float a, float b) {
    asm volatile("red.global.add.v2.f32 [%0], {%1, %2};"
                 :: "l"(p), "f"(a), "f"(b) : "memory");
}
// raw biased dequant: byte b (2 nibbles) -> fp16x2 {lo = 1024+lo_nib (even k),
// hi = 1024+hi_nib (odd k)}. Exact in fp16. 3 ALU ops.
__device__ __forceinline__ unsigned dqraw(int b) {
    unsigned t = (unsigned)b | ((unsigned)b << 12);
    return (t & 0x000F000Fu) | 0x64006400u;
}

// merged prologue: blocks 0..1023 init out=bias; blocks 1024..1055 compute X sums
__global__ void __launch_bounds__(NTHREADS)
gptq_pre(const float* __restrict__ bias, float* __restrict__ out,
         const float* __restrict__ x) {
    const int bid = blockIdx.x;
    const int t = threadIdx.x;
    if (bid < (MM * NDIM) / NTHREADS) {
        int i = bid * NTHREADS + t;
        out[i] = bias[i & (NDIM - 1)];
        return;
    }
    // X sums: one block per m row. thread t handles float4 idx t + 256*i;
    // group(f4) = (t>>4) + 16*i; 16-thread shfl clusters reduce.
    const int m = bid - (MM * NDIM) / NTHREADS;
    const int l = t & 31;
    const float4* xr = reinterpret_cast<const float4*>(x + (size_t)m * KDIM);
    float s[8];
#pragma unroll
    for (int i = 0; i < 8; ++i) {
        float4 v = xr[t + 256 * i];
        __half2 h0 = __floats2half2_rn(v.x, v.y);
        __half2 h1 = __floats2half2_rn(v.z, v.w);
        float2 f0 = __half22float2(h0);
        float2 f1 = __half22float2(h1);
        s[i] = (f0.x + f0.y) + (f1.x + f1.y);
    }
#pragma unroll
    for (int mask = 1; mask < 16; mask <<= 1)
#pragma unroll
        for (int i = 0; i < 8; ++i)
            s[i] += __shfl_xor_sync(0xFFFFFFFFu, s[i], mask);
    const int j = l & 15;
    if (j < 8) {
        const int g = (t >> 4) + 16 * j;
        d_Xg[g * MM + m] = s[j];
    }
}

extern __shared__ char smem_raw[];

__global__ void __launch_bounds__(NTHREADS, 3)
gptq_main(const float* __restrict__ x, const int* __restrict__ pw,
          const float* __restrict__ scales, const float* __restrict__ zeros,
          float* __restrict__ out)
{
    int* ws = reinterpret_cast<int*>(smem_raw);                        // [2][128][32], swizzled
    __half* xs = reinterpret_cast<__half*>(smem_raw + WS_BYTES);       // [32][512], swizzled
    float* xsum = reinterpret_cast<float*>(smem_raw + WS_BYTES + XS_BYTES); // [8][32]
    float* c2s = xsum + GROUPS_PER * 32;                               // [8][128] z+1024
    float* rqs = c2s + GROUPS_PER * NBLK;                              // [8][128] ratio

    const int tid = threadIdx.x;
    const int w = tid >> 5;
    const int l = tid & 31;
    const int nblock0 = blockIdx.x * NBLK;
    const int k0 = blockIdx.y * KPER;
    const int g0 = blockIdx.y * GROUPS_PER;

    const unsigned ws_base = smem_u32(ws);

    // weight staging: 1024 16B units per group; thread -> (row = tid>>3 + 32i, ch = tid&7)
    // swizzled dst chunk = ch ^ (row&7); (row&7) constant across i.
    const int s_ch  = tid & 7;
    const int s_row = tid >> 3;
    const int s_swz = s_ch ^ (s_row & 7);

    auto stage_w = [&](int g, int b) {
        const int* gsrc = pw + ((k0 + g * GS) >> 1) + s_ch * 4;
        unsigned sdst = ws_base + (unsigned)(b * WBUF * 4 + s_row * 128 + s_swz * 16);
#pragma unroll
        for (int i = 0; i < 4; ++i)
            cp_async16(sdst + (unsigned)(i * 32 * 128),
                       gsrc + (size_t)(nblock0 + s_row + i * 32) * (KDIM / 2));
        cp_commit();
    };
    stage_w(0, 0);
    stage_w(1, 1);

    // ---- stage x: fp32 -> fp16, swizzled rows (1024B stride, chunk16 ^= m&7) ----
    {
#pragma unroll
        for (int i = 0; i < 16; ++i) {
            int lin = tid + i * NTHREADS;  // 0..4095 float4s
            int v = lin & 127;             // float4 idx along k; 8B unit = v
            int m = lin >> 7;
            float4 xv = *reinterpret_cast<const float4*>(x + (size_t)m * KDIM + k0 + 4 * v);
            __half2 h0 = __floats2half2_rn(xv.x, xv.y);
            __half2 h1 = __floats2half2_rn(xv.z, xv.w);
            uint2 pr;
            pr.x = *reinterpret_cast<unsigned*>(&h0);
            pr.y = *reinterpret_cast<unsigned*>(&h1);
            unsigned byte_off = (unsigned)(m * 1024 + (((v >> 1) ^ (m & 7)) << 4) + (v & 1) * 8);
            *reinterpret_cast<uint2*>(reinterpret_cast<char*>(xs) + byte_off) = pr;
        }
    }

    // ---- X LUT slice: one coalesced LDG per thread ----
    xsum[tid] = __ldg(&d_Xg[(g0 + (tid >> 5)) * MM + (tid & 31)]);

    // ---- fill LUTs: c2[g][n] = z+1024; rq[g][n] = s_g/s_{g+1} (g<7), s_7 (g==7) ----
#pragma unroll
    for (int i = 0; i < 4; ++i) {
        int lin = tid + i * NTHREADS;   // 0..1023
        int g = lin & 7;
        int n = lin >> 3;               // 0..127
        const float* srow = scales + (size_t)(nblock0 + n) * NGROUPS + g0;
        float s = __ldg(srow + g);
        float z = __ldg(zeros + (size_t)(nblock0 + n) * NGROUPS + g0 + g);
        float rq;
        if (g < GROUPS_PER - 1) {
            float sn = __ldg(srow + g + 1);
            rq = __fdividef(s, sn);
        } else {
            rq = s;                     // last group: convert to output units
        }
        c2s[g * NBLK + n] = z + 1024.0f;
        rqs[g * NBLK + n] = rq;
    }

    // ldsm lane geometry: row = l&15 (+16 for second m-tile), k-half hk = l>>4,
    // swizzle XOR = row&7 = l&7 (same for row and row+16).
    const unsigned xs_base = smem_u32(xs);
    const unsigned xrow0 = xs_base + (unsigned)((l & 15) * 1024);
    const unsigned xrow1 = xrow0 + 16u * 1024u;
    const int hk = l >> 4;
    const int lw = l & 7;

    // weight LDS geometry: rows w*16 + (l>>2) and +8; swizzle XOR = l>>2 for both.
    const int xw = l >> 2;
    const int wbase0 = (w * 16 + (l >> 2)) * 32 + (l & 3);    // int32 idx, chunk added per step
    const int wbase1 = wbase0 + 8 * 32;

    // accumulator column base within CTA: n_local = w*16 + tn*8 + 2*(l&3) + (e&1)
    const int ncol = w * 16 + 2 * (l & 3);

    float acc[2][2][4] = {};   // [m-tile][n-tile][frag] in running s_g units

#pragma unroll
    for (int g = 0; g < GROUPS_PER; ++g) {
        if (g == GROUPS_PER - 1) cp_wait<0>(); else cp_wait<1>();
        __syncthreads();

        const int bufo = (g & 1) * WBUF;

#pragma unroll
        for (int s4 = 0; s4 < 4; ++s4) {
            const int s = g * 4 + s4;          // global k16-step
            // A frags: chunk16 = 2s + hk, swizzled ^ lw
            unsigned xoff = (unsigned)(((2 * s + hk) ^ lw) << 4);
            unsigned a0[4], a1[4];
            ldsm4(a0[0], a0[1], a0[2], a0[3], xrow0 + xoff);
            ldsm4(a1[0], a1[1], a1[2], a1[3], xrow1 + xoff);

            // weights: chunks 2*s4 and 2*s4+1, swizzled ^ xw (per-lane)
            const int c0 = ((2 * s4)     ^ xw) * 4;
            const int c1 = ((2 * s4 + 1) ^ xw) * 4;
            unsigned b0[2], b1[2];
            b0[0] = dqraw(ws[bufo + wbase0 + c0]);
            b0[1] = dqraw(ws[bufo + wbase0 + c1]);
            b1[0] = dqraw(ws[bufo + wbase1 + c0]);
            b1[1] = dqraw(ws[bufo + wbase1 + c1]);

            mma16816(acc[0][0], a0, b0);
            mma16816(acc[0][1], a0, b1);
            mma16816(acc[1][0], a1, b0);
            mma16816(acc[1][1], a1, b1);
        }

        // end-of-group: acc = (acc - (z+1024)*X_g[row]) * rq  (column-correct LUTs)
        {
            const float* xg = xsum + g * 32 + (l >> 2);
            float Xv[4];
            Xv[0] = xg[0];  Xv[1] = xg[8];   // m-tile 0: rows r, r+8
            Xv[2] = xg[16]; Xv[3] = xg[24];  // m-tile 1
            const float* c2g = c2s + g * NBLK + ncol;
            const float* rqg = rqs + g * NBLK + ncol;
            float c2v[4], rqv[4];
            c2v[0] = c2g[0]; c2v[1] = c2g[1]; c2v[2] = c2g[8]; c2v[3] = c2g[9];
            rqv[0] = rqg[0]; rqv[1] = rqg[1]; rqv[2] = rqg[8]; rqv[3] = rqg[9];
#pragma unroll
            for (int tm = 0; tm < 2; ++tm)
#pragma unroll
                for (int tn = 0; tn < 2; ++tn)
#pragma unroll
                    for (int e = 0; e < 4; ++e) {
                        const float Xe = Xv[tm * 2 + (e >> 1)];
                        const float c2e = c2v[tn * 2 + (e & 1)];
                        const float rqe = rqv[tn * 2 + (e & 1)];
                        acc[tm][tn][e] = fmaf(-c2e, Xe, acc[tm][tn][e]) * rqe;
                    }
        }

        if (g < GROUPS_PER - 2) {
            __syncthreads();           // all warps done reading buffer g&1
            stage_w(g + 2, g & 1);
        }
    }

    // ---- epilogue: K-split partials via vector reductions (already scaled) ----
#pragma unroll
    for (int tm = 0; tm < 2; ++tm) {
#pragma unroll
        for (int tn = 0; tn < 2; ++tn) {
            const int n = nblock0 + w * 16 + tn * 8 + (l & 3) * 2;
            const int m = tm * 16 + (l >> 2);
            red2(out + (size_t)m * NDIM + n,       acc[tm][tn][0], acc[tm][tn][1]);
            red2(out + (size_t)(m + 8) * NDIM + n, acc[tm][tn][2], acc[tm][tn][3]);
        }
    }
}

extern "C" void kernel_launch(void* const* d_in, const int* in_sizes, int n_in,
                              void* d_out, int out_size) {
    const float* x      = (const float*)d_in[0];
    const int*   pw     = (const int*)d_in[1];
    const float* scales = (const float*)d_in[2];
    const float* zeros  = (const float*)d_in[3];
    const float* bias   = (const float*)d_in[4];
    float* out = (float*)d_out;

    // merged prologue: out=bias init (1024 blocks) + X group sums (32 blocks)
    gptq_pre<<<(MM * NDIM) / NTHREADS + MM, NTHREADS>>>(bias, out, x);

    cudaFuncSetAttribute(gptq_main, cudaFuncAttributeMaxDynamicSharedMemorySize,
                         SMEM_TOTAL);
    dim3 grid(NDIM / NBLK, KSPLIT);
    gptq_main<<<grid, NTHREADS, SMEM_TOTAL>>>(x, pw, scales, zeros, out);
}